// round 11
// baseline (speedup 1.0000x reference)
#include <cuda_runtime.h>
#include <cuda_fp16.h>
#include <cstdint>

// VectorQuantStraightThrough via warp-level HMMA (mma.sync m16n8k16 fp16),
// fp32-emulated dot with fp16 2-way splits, 3 cross terms, single 12-deep
// accumulator chain (round-5 style; warps provide latency hiding).
//   z scaled 2^3, e scaled 2^15 => accum = 2^18*dot; 2*dot = accum*2^-17 exact.
//   d2 = fl( fl(z2 - 2dot) + e2 )  (reference fp32 rounding replicated).
// Round 11: codebook quarter-split (128 codes/CTA), 65KB smem + <=84 regs
// => 3 CTAs/SM (6 warps/SMSP). In-CTA e-split conversion (prep kernel gone).
// ldmatrix.x4 fragment loads. 4-way merge kernel writes outputs.

#define NROWS (32 * 4096)   // 131072
#define DDIM  64
#define KCB   512
#define KQ    128           // codes per CTA (one quarter)
#define MT    128           // rows per tile
#define NTILES (NROWS / MT) // 1024
#define CTAS_PER_Q 111
#define GRID_MAIN (4 * CTAS_PER_Q)  // 444 persistent (3/SM)
#define TPB   256

// smem byte offsets (unpadded 128B rows, XOR-swizzled by (row&7)<<4)
#define SM_B0   0           // e-split0 [128][64] half   16384 B
#define SM_B1   16384       // e-split1
#define SM_A0   32768       // z-split0 [128][64] half
#define SM_A1   49152       // z-split1
#define SM_E2   65536       // e2 quarter [128] float
#define SM_Z2   66048       // z2 [128] float
#define SM_TOTAL 66560

#define TWO_DOT_SCALE (1.0f / 131072.0f)   // 2^-17

// ---- device scratch: per-quarter partial argmin ----
__device__ float2 g_part[4][NROWS];   // (best_d, best_global_idx as float)

__device__ __forceinline__ uint32_t smem_u32(const void* p) {
    uint32_t a;
    asm("{ .reg .u64 t; cvta.to.shared.u64 t, %1; cvt.u32.u64 %0, t; }"
        : "=r"(a) : "l"(p));
    return a;
}

__device__ __forceinline__ void mma16816(float* c, const uint32_t* a,
                                         const uint32_t* b) {
    asm volatile(
        "mma.sync.aligned.m16n8k16.row.col.f32.f16.f16.f32 "
        "{%0,%1,%2,%3}, {%4,%5,%6,%7}, {%8,%9}, {%0,%1,%2,%3};"
        : "+f"(c[0]), "+f"(c[1]), "+f"(c[2]), "+f"(c[3])
        : "r"(a[0]), "r"(a[1]), "r"(a[2]), "r"(a[3]), "r"(b[0]), "r"(b[1]));
}

#define LDSM4(d, a) \
    asm volatile("ldmatrix.sync.aligned.m8n8.x4.shared.b16 {%0,%1,%2,%3}, [%4];" \
        : "=r"((d)[0]), "=r"((d)[1]), "=r"((d)[2]), "=r"((d)[3]) : "r"(a))

// ---------------- main persistent kernel (one codebook quarter per CTA) ----
__global__ __launch_bounds__(TPB, 3)
void vq_main_kernel(const float* __restrict__ z,
                    const float* __restrict__ emb) {
    extern __shared__ char smem[];
    const uint32_t sb = smem_u32(smem);
    const int tid = threadIdx.x;
    const int w   = tid >> 5;
    const int l   = tid & 31;
    const int quarter = blockIdx.x & 3;
    const int ctaq    = blockIdx.x >> 2;     // 0..110
    const int r  = l & 7;
    const int mm = l >> 3;
    const int lr = l >> 2;
    const int kb = (l & 3) * 2;

    // ---- prologue (once per CTA): convert quarter's codes -> B splits + e2
    if (tid < KQ) {
        const float4* src =
            (const float4*)(emb + (size_t)(quarter * KQ + tid) * DDIM);
        const int txor = (tid & 7) << 4;
        char* b0 = smem + SM_B0 + tid * 128;
        char* b1 = smem + SM_B1 + tid * 128;
        float s = 0.f;
        #pragma unroll
        for (int q = 0; q < 16; q++) {
            const float4 v = src[q];
            // e2 chain: sequential d ascending (exact passing order)
            s = fmaf(v.x, v.x, s); s = fmaf(v.y, v.y, s);
            s = fmaf(v.z, v.z, s); s = fmaf(v.w, v.w, s);
            const float sx = v.x * 32768.0f, sy = v.y * 32768.0f;
            const float sz = v.z * 32768.0f, sw = v.w * 32768.0f;
            const __half hx0 = __float2half_rn(sx);
            const __half hy0 = __float2half_rn(sy);
            const __half hz0 = __float2half_rn(sz);
            const __half hw0 = __float2half_rn(sw);
            const __half hx1 = __float2half_rn(sx - __half2float(hx0));
            const __half hy1 = __float2half_rn(sy - __half2float(hy0));
            const __half hz1 = __float2half_rn(sz - __half2float(hz0));
            const __half hw1 = __float2half_rn(sw - __half2float(hw0));
            const uint32_t o0 = (uint32_t)(8 * q) ^ txor;
            const uint32_t o1 = (uint32_t)(8 * q + 4) ^ txor;
            *(__half2*)(b0 + o0) = __halves2half2(hx0, hy0);
            *(__half2*)(b0 + o1) = __halves2half2(hz0, hw0);
            *(__half2*)(b1 + o0) = __halves2half2(hx1, hy1);
            *(__half2*)(b1 + o1) = __halves2half2(hz1, hw1);
        }
        ((float*)(smem + SM_E2))[tid] = s;
    }

    const float* e2s = (const float*)(smem + SM_E2);
    const float* z2s = (const float*)(smem + SM_Z2);
    const int mrow0 = w * 16;                      // 8 warps x 16 rows
    const uint32_t rowA = (uint32_t)(mrow0 + (mm & 1) * 8 + r);
    const uint32_t xr   = (uint32_t)(r << 4);
    const uint32_t cA   = (uint32_t)((mm >> 1) * 16);      // + kt*32, then ^xr
    const uint32_t cB0c = ((uint32_t)(mm * 16)) ^ xr;      // ktp=0 col const
    const uint32_t cB1c = ((uint32_t)(64 + mm * 16)) ^ xr; // ktp=1 col const

    // ---- persistent tile loop ----
    for (int tile = ctaq; tile < NTILES; tile += CTAS_PER_Q) {
        __syncthreads();   // B/e2 visible (iter 0); protect A/z2 reuse (iter>0)

        // threads 0..127: own one z row — stream from global, compute z2
        // in the EXACT passing order, emit fp16 splits (scaled 2^3) swizzled.
        if (tid < MT) {
            const float4* zr =
                (const float4*)(z + ((size_t)tile * MT + tid) * DDIM);
            const int txor = (tid & 7) << 4;
            char* a0 = smem + SM_A0 + tid * 128;
            char* a1 = smem + SM_A1 + tid * 128;
            float c[8] = {0.f, 0.f, 0.f, 0.f, 0.f, 0.f, 0.f, 0.f};
            #pragma unroll
            for (int q = 0; q < 16; q++) {
                const float4 v = zr[q];
                c[(4 * q + 0) & 7] = fmaf(v.x, v.x, c[(4 * q + 0) & 7]);
                c[(4 * q + 1) & 7] = fmaf(v.y, v.y, c[(4 * q + 1) & 7]);
                c[(4 * q + 2) & 7] = fmaf(v.z, v.z, c[(4 * q + 2) & 7]);
                c[(4 * q + 3) & 7] = fmaf(v.w, v.w, c[(4 * q + 3) & 7]);
                const float sx = v.x * 8.0f, sy = v.y * 8.0f;
                const float sz = v.z * 8.0f, sw = v.w * 8.0f;
                const __half hx0 = __float2half_rn(sx);
                const __half hy0 = __float2half_rn(sy);
                const __half hz0 = __float2half_rn(sz);
                const __half hw0 = __float2half_rn(sw);
                const __half hx1 = __float2half_rn(sx - __half2float(hx0));
                const __half hy1 = __float2half_rn(sy - __half2float(hy0));
                const __half hz1 = __float2half_rn(sz - __half2float(hz0));
                const __half hw1 = __float2half_rn(sw - __half2float(hw0));
                const uint32_t o0 = (uint32_t)(8 * q) ^ txor;
                const uint32_t o1 = (uint32_t)(8 * q + 4) ^ txor;
                *(__half2*)(a0 + o0) = __halves2half2(hx0, hy0);
                *(__half2*)(a0 + o1) = __halves2half2(hz0, hw0);
                *(__half2*)(a1 + o0) = __halves2half2(hx1, hy1);
                *(__half2*)(a1 + o1) = __halves2half2(hz1, hw1);
            }
            const float lo = __fadd_rn(__fadd_rn(c[0], c[2]), __fadd_rn(c[4], c[6]));
            const float hi = __fadd_rn(__fadd_rn(c[1], c[3]), __fadd_rn(c[5], c[7]));
            ((float*)(smem + SM_Z2))[tid] = __fadd_rn(lo, hi);
        }
        __syncthreads();

        // A-split0 fragments via ldmatrix.x4 (held for whole j-loop)
        uint32_t Af[4][4];
        {
            const uint32_t baseA0 = sb + SM_A0 + rowA * 128;
            #pragma unroll
            for (int kt = 0; kt < 4; kt++) {
                const uint32_t col = ((uint32_t)(kt * 32) + cA) ^ xr;
                LDSM4(Af[kt], baseA0 + col);
            }
        }
        const float z2a = z2s[mrow0 + lr];
        const float z2b = z2s[mrow0 + lr + 8];
        float bv0 = 3.4e38f, bv1 = 3.4e38f;
        int   bi0 = 0, bi1 = 0;

        uint32_t bB0 = sb + SM_B0 + r * 128;
        uint32_t bB1 = sb + SM_B1 + r * 128;
        const uint32_t baseA1 = sb + SM_A1 + rowA * 128;

        // ---- main loop: 16 n-tiles (8 codes each) over this quarter ----
        #pragma unroll 2
        for (int j = 0; j < 16; j++) {
            uint32_t B0[8], B1[8];   // [2*kt+h]
            LDSM4(&B0[0], bB0 + cB0c);
            LDSM4(&B0[4], bB0 + cB1c);
            LDSM4(&B1[0], bB1 + cB0c);
            LDSM4(&B1[4], bB1 + cB1c);
            bB0 += 1024; bB1 += 1024;

            float C[4] = {0.f, 0.f, 0.f, 0.f};
            // small terms first: a0*b1 and a1*b0 interleaved, then a0*b0
            #pragma unroll
            for (int kt = 0; kt < 4; kt++) {
                uint32_t A1f[4];
                const uint32_t col = ((uint32_t)(kt * 32) + cA) ^ xr;
                LDSM4(A1f, baseA1 + col);
                mma16816(C, Af[kt], &B1[2 * kt]);   // a0*b1
                mma16816(C, A1f,    &B0[2 * kt]);   // a1*b0
            }
            #pragma unroll
            for (int kt = 0; kt < 4; kt++)
                mma16816(C, Af[kt], &B0[2 * kt]);   // a0*b0 (dominant, last)

            // epilogue: reference rounding, running argmin (r5 formula)
            const int ca = j * 8 + kb;
            const float e2a = e2s[ca], e2b = e2s[ca + 1];
            const float d00 = __fadd_rn(__fsub_rn(z2a, C[0] * TWO_DOT_SCALE), e2a);
            const float d01 = __fadd_rn(__fsub_rn(z2a, C[1] * TWO_DOT_SCALE), e2b);
            const float d10 = __fadd_rn(__fsub_rn(z2b, C[2] * TWO_DOT_SCALE), e2a);
            const float d11 = __fadd_rn(__fsub_rn(z2b, C[3] * TWO_DOT_SCALE), e2b);
            if (d00 < bv0) { bv0 = d00; bi0 = ca; }
            if (d01 < bv0) { bv0 = d01; bi0 = ca + 1; }
            if (d10 < bv1) { bv1 = d10; bi1 = ca; }
            if (d11 < bv1) { bv1 = d11; bi1 = ca + 1; }
        }

        // quad reduce (min, lowest index on tie), write partials to global
        #pragma unroll
        for (int h = 0; h < 2; h++) {
            float v = h ? bv1 : bv0;
            int   i = h ? bi1 : bi0;
            #pragma unroll
            for (int s = 1; s <= 2; s <<= 1) {
                const float ov = __shfl_xor_sync(0xFFFFFFFFu, v, s);
                const int   oi = __shfl_xor_sync(0xFFFFFFFFu, i, s);
                if (ov < v || (ov == v && oi < i)) { v = ov; i = oi; }
            }
            if ((l & 3) == 0) {
                const int row = mrow0 + lr + h * 8;
                g_part[quarter][(size_t)tile * MT + row] =
                    make_float2(v, (float)(quarter * KQ + i));
            }
        }
    }
}

// ---------------- merge quarters, gather codes, write outputs --------------
#define B_ROWS_PER_CTA 16
#define GRID_B (NROWS / B_ROWS_PER_CTA)   // 8192

__global__ __launch_bounds__(TPB, 8)
void vq_merge_gather_kernel(const float* __restrict__ emb,
                            float* __restrict__ out,
                            long long out_size) {
    __shared__ int sidx[B_ROWS_PER_CTA];

    const int tid  = threadIdx.x;
    const int rloc = tid >> 4;
    const int q    = tid & 15;
    const long long row0 = (long long)blockIdx.x * B_ROWS_PER_CTA;

    if (tid < B_ROWS_PER_CTA) {
        const long long n = row0 + tid;
        float2 best = g_part[0][n];
        #pragma unroll
        for (int qq = 1; qq < 4; qq++) {     // ascending quarter, strict <
            const float2 p = g_part[qq][n];  // => first-index tiebreak
            if (p.x < best.x) best = p;
        }
        sidx[tid] = (int)best.y;
    }
    __syncthreads();

    const long long n   = row0 + rloc;
    const int idx       = sidx[rloc];
    const float4 v      = ((const float4*)(emb + (long long)idx * DDIM))[q];
    const long long ND  = (long long)NROWS * DDIM;
    const long long off = n * DDIM + q * 4;

    if (out_size >= ND)      *((float4*)(out + off))      = v;  // z_q_st
    if (out_size >= 2 * ND)  *((float4*)(out + ND + off)) = v;  // z_q

    if (q == 0) {   // indices as float (0..511 exact)
        if (out_size >= 2 * ND + NROWS)      out[2 * ND + n] = (float)idx;
        else if (out_size == ND + NROWS)     out[ND + n]     = (float)idx;
        else if (out_size == NROWS)          out[n]          = (float)idx;
    }
}

// ---------------------------------------------------------------------------
extern "C" void kernel_launch(void* const* d_in, const int* in_sizes, int n_in,
                              void* d_out, int out_size) {
    const float* z   = (const float*)d_in[0];
    const float* emb = (const float*)d_in[1];
    if (n_in >= 2 && in_sizes[0] == KCB * DDIM && in_sizes[1] == NROWS * DDIM) {
        z   = (const float*)d_in[1];
        emb = (const float*)d_in[0];
    }

    static int configured = -1;
    if (configured < 0) {
        cudaFuncSetAttribute(vq_main_kernel,
                             cudaFuncAttributeMaxDynamicSharedMemorySize, SM_TOTAL);
        configured = 1;
    }

    vq_main_kernel<<<GRID_MAIN, TPB, SM_TOTAL>>>(z, emb);
    vq_merge_gather_kernel<<<GRID_B, TPB>>>(emb, (float*)d_out,
                                            (long long)out_size);
}

// round 17
// speedup vs baseline: 1.0482x; 1.0482x over previous
#include <cuda_runtime.h>
#include <cuda_fp16.h>
#include <cstdint>

// VectorQuantStraightThrough via warp-level HMMA (mma.sync m16n8k16 fp16),
// fp32-emulated dot with fp16 2-way splits, 3 cross terms.
//   z scaled 2^3, e scaled 2^15 => accum = 2^18*dot; 2*dot = accum*2^-17 exact.
//   d2 = fl( fl(z2 - 2dot) + e2 )  (reference fp32 rounding replicated).
// Round 17: r13 with the copy-loop overrun fixed (2048 uint4 = 32 KB image,
// was 4096 -> smem OOB -> illegal memory access). Numerics identical to
// passing rounds.

#define NROWS (32 * 4096)   // 131072
#define DDIM  64
#define KCB   512
#define KQ    128           // codes per CTA (one quarter)
#define MT    128           // rows per tile
#define NTILES (NROWS / MT) // 1024
#define CTAS_PER_Q 111
#define GRID_MAIN (4 * CTAS_PER_Q)  // 444 persistent (3/SM)
#define TPB   256

// main-kernel smem offsets (unpadded 128B rows, XOR-swizzled by (row&7)<<4)
#define SM_B0   0           // e-split0 [128][64] half   16384 B
#define SM_B1   16384       // e-split1
#define SM_A0   32768       // z-split0 image (16384 B)
#define SM_A1   49152       // z-split1 image (contiguous with A0)
#define SM_E2   65536       // e2 quarter [128] float
#define SM_Z2   66048       // z2 [128] float
#define SM_TOTAL 66560

// zprep dynamic-smem offsets
#define ZP_ZT   0           // fp32 tile [128][64]  32768 B
#define ZP_SP   32768       // split images 2 x 16384 B
#define ZP_TOTAL 65536

#define TWO_DOT_SCALE (1.0f / 131072.0f)   // 2^-17

// ---- device scratch ----
__device__ __align__(16) char g_za[NTILES * 32768];  // swizzled split images (32 MB)
__device__ float  g_z2[NROWS];
__device__ float2 g_part[4][NROWS];   // per-quarter (best_d, best_global_idx)

__device__ __forceinline__ uint32_t smem_u32(const void* p) {
    uint32_t a;
    asm("{ .reg .u64 t; cvta.to.shared.u64 t, %1; cvt.u32.u64 %0, t; }"
        : "=r"(a) : "l"(p));
    return a;
}

__device__ __forceinline__ void mma16816(float* c, const uint32_t* a,
                                         const uint32_t* b) {
    asm volatile(
        "mma.sync.aligned.m16n8k16.row.col.f32.f16.f16.f32 "
        "{%0,%1,%2,%3}, {%4,%5,%6,%7}, {%8,%9}, {%0,%1,%2,%3};"
        : "+f"(c[0]), "+f"(c[1]), "+f"(c[2]), "+f"(c[3])
        : "r"(a[0]), "r"(a[1]), "r"(a[2]), "r"(a[3]), "r"(b[0]), "r"(b[1]));
}

#define LDSM4(d, a) \
    asm volatile("ldmatrix.sync.aligned.m8n8.x4.shared.b16 {%0,%1,%2,%3}, [%4];" \
        : "=r"((d)[0]), "=r"((d)[1]), "=r"((d)[2]), "=r"((d)[3]) : "r"(a))

// ---------------- z-prep: fp16 splits (swizzled image) + z2, once per tile --
__global__ __launch_bounds__(TPB, 1)
void vq_zprep_kernel(const float* __restrict__ z) {
    extern __shared__ char zsm[];
    float* zt = (float*)(zsm + ZP_ZT);
    char*  sp = zsm + ZP_SP;
    const int tid  = threadIdx.x;
    const int tile = blockIdx.x;

    // stage fp32 tile coalesced
    {
        const float4* src = (const float4*)(z + (size_t)tile * MT * DDIM);
        float4* dst = (float4*)zt;
        #pragma unroll
        for (int i = tid; i < MT * DDIM / 4; i += TPB) dst[i] = src[i];
    }
    __syncthreads();

    // convert: each thread does half a row (32 elems = 8 float4)
    {
        const int row = tid >> 1, h = tid & 1;
        const int txor = (row & 7) << 4;
        char* a0 = sp + row * 128;            // split0 image
        char* a1 = sp + 16384 + row * 128;    // split1 image
        const float4* zr = (const float4*)(zt + row * DDIM) + h * 8;
        #pragma unroll
        for (int q = 0; q < 8; q++) {
            const float4 v = zr[q];
            const float sx = v.x * 8.0f, sy = v.y * 8.0f;
            const float sz = v.z * 8.0f, sw = v.w * 8.0f;
            const __half hx0 = __float2half_rn(sx);
            const __half hy0 = __float2half_rn(sy);
            const __half hz0 = __float2half_rn(sz);
            const __half hw0 = __float2half_rn(sw);
            const __half hx1 = __float2half_rn(sx - __half2float(hx0));
            const __half hy1 = __float2half_rn(sy - __half2float(hy0));
            const __half hz1 = __float2half_rn(sz - __half2float(hz0));
            const __half hw1 = __float2half_rn(sw - __half2float(hw0));
            const int qq = h * 8 + q;
            const uint32_t o0 = (uint32_t)(8 * qq) ^ txor;
            const uint32_t o1 = (uint32_t)(8 * qq + 4) ^ txor;
            *(__half2*)(a0 + o0) = __halves2half2(hx0, hy0);
            *(__half2*)(a0 + o1) = __halves2half2(hz0, hw0);
            *(__half2*)(a1 + o0) = __halves2half2(hx1, hy1);
            *(__half2*)(a1 + o1) = __halves2half2(hz1, hw1);
        }
    }
    // z2 per row: EXACT passing evaluation order (element e -> c[e&7], asc.)
    if (tid < MT) {
        const float4* zr = (const float4*)(zt + tid * DDIM);
        float c[8] = {0.f, 0.f, 0.f, 0.f, 0.f, 0.f, 0.f, 0.f};
        #pragma unroll
        for (int q = 0; q < 16; q++) {
            const float4 v = zr[q];
            c[(4 * q + 0) & 7] = fmaf(v.x, v.x, c[(4 * q + 0) & 7]);
            c[(4 * q + 1) & 7] = fmaf(v.y, v.y, c[(4 * q + 1) & 7]);
            c[(4 * q + 2) & 7] = fmaf(v.z, v.z, c[(4 * q + 2) & 7]);
            c[(4 * q + 3) & 7] = fmaf(v.w, v.w, c[(4 * q + 3) & 7]);
        }
        const float lo = __fadd_rn(__fadd_rn(c[0], c[2]), __fadd_rn(c[4], c[6]));
        const float hi = __fadd_rn(__fadd_rn(c[1], c[3]), __fadd_rn(c[5], c[7]));
        g_z2[tile * MT + tid] = __fadd_rn(lo, hi);
    }
    __syncthreads();

    // copy swizzled images to global (2048 x uint4 = 32 KB)
    {
        uint4* dst = (uint4*)(g_za + (size_t)tile * 32768);
        const uint4* s0 = (const uint4*)sp;
        #pragma unroll
        for (int i = tid; i < 2048; i += TPB) dst[i] = s0[i];
    }
}

// ---------------- main persistent kernel (one codebook quarter per CTA) ----
__global__ __launch_bounds__(TPB, 3)
void vq_main_kernel(const float* __restrict__ emb) {
    extern __shared__ char smem[];
    const uint32_t sb = smem_u32(smem);
    const int tid = threadIdx.x;
    const int w   = tid >> 5;
    const int l   = tid & 31;
    const int quarter = blockIdx.x & 3;
    const int ctaq    = blockIdx.x >> 2;     // 0..110
    const int r  = l & 7;
    const int mm = l >> 3;
    const int lr = l >> 2;
    const int kb = (l & 3) * 2;

    // ---- prologue (once per CTA): convert quarter's codes -> B splits + e2
    if (tid < KQ) {
        const float4* src =
            (const float4*)(emb + (size_t)(quarter * KQ + tid) * DDIM);
        const int txor = (tid & 7) << 4;
        char* b0 = smem + SM_B0 + tid * 128;
        char* b1 = smem + SM_B1 + tid * 128;
        float s = 0.f;
        #pragma unroll
        for (int q = 0; q < 16; q++) {
            const float4 v = src[q];
            s = fmaf(v.x, v.x, s); s = fmaf(v.y, v.y, s);  // exact e2 order
            s = fmaf(v.z, v.z, s); s = fmaf(v.w, v.w, s);
            const float sx = v.x * 32768.0f, sy = v.y * 32768.0f;
            const float sz = v.z * 32768.0f, sw = v.w * 32768.0f;
            const __half hx0 = __float2half_rn(sx);
            const __half hy0 = __float2half_rn(sy);
            const __half hz0 = __float2half_rn(sz);
            const __half hw0 = __float2half_rn(sw);
            const __half hx1 = __float2half_rn(sx - __half2float(hx0));
            const __half hy1 = __float2half_rn(sy - __half2float(hy0));
            const __half hz1 = __float2half_rn(sz - __half2float(hz0));
            const __half hw1 = __float2half_rn(sw - __half2float(hw0));
            const uint32_t o0 = (uint32_t)(8 * q) ^ txor;
            const uint32_t o1 = (uint32_t)(8 * q + 4) ^ txor;
            *(__half2*)(b0 + o0) = __halves2half2(hx0, hy0);
            *(__half2*)(b0 + o1) = __halves2half2(hz0, hw0);
            *(__half2*)(b1 + o0) = __halves2half2(hx1, hy1);
            *(__half2*)(b1 + o1) = __halves2half2(hz1, hw1);
        }
        ((float*)(smem + SM_E2))[tid] = s;
    }

    const float* e2s = (const float*)(smem + SM_E2);
    const float* z2s = (const float*)(smem + SM_Z2);
    const int mrow0 = w * 16;                      // 8 warps x 16 rows
    const uint32_t rowA = (uint32_t)(mrow0 + (mm & 1) * 8 + r);
    const uint32_t xr   = (uint32_t)(r << 4);
    const uint32_t cA   = (uint32_t)((mm >> 1) * 16);      // + kt*32, then ^xr
    const uint32_t cB0c = ((uint32_t)(mm * 16)) ^ xr;
    const uint32_t cB1c = ((uint32_t)(64 + mm * 16)) ^ xr;

    // ---- persistent tile loop ----
    for (int tile = ctaq; tile < NTILES; tile += CTAS_PER_Q) {
        __syncthreads();   // B/e2 visible (iter 0); protect A/z2 reuse (iter>0)

        // pure copy: precomputed swizzled split images (2048 uint4) + z2
        {
            const uint4* src = (const uint4*)(g_za + (size_t)tile * 32768);
            uint4* dst = (uint4*)(smem + SM_A0);   // A0|A1 contiguous, 32 KB
            #pragma unroll
            for (int i = tid; i < 2048; i += TPB) dst[i] = src[i];
            if (tid < MT)
                ((float*)(smem + SM_Z2))[tid] = g_z2[tile * MT + tid];
        }
        __syncthreads();

        // A-split0 fragments via ldmatrix.x4 (held for whole j-loop)
        uint32_t Af[4][4];
        {
            const uint32_t baseA0 = sb + SM_A0 + rowA * 128;
            #pragma unroll
            for (int kt = 0; kt < 4; kt++) {
                const uint32_t col = ((uint32_t)(kt * 32) + cA) ^ xr;
                LDSM4(Af[kt], baseA0 + col);
            }
        }
        const float z2a = z2s[mrow0 + lr];
        const float z2b = z2s[mrow0 + lr + 8];
        float bv0 = 3.4e38f, bv1 = 3.4e38f;
        int   bi0 = 0, bi1 = 0;

        uint32_t bB0 = sb + SM_B0 + r * 128;
        uint32_t bB1 = sb + SM_B1 + r * 128;
        const uint32_t baseA1 = sb + SM_A1 + rowA * 128;

        // ---- main loop: 16 n-tiles (8 codes each) over this quarter ----
        #pragma unroll 2
        for (int j = 0; j < 16; j++) {
            uint32_t B0[8], B1[8];
            LDSM4(&B0[0], bB0 + cB0c);
            LDSM4(&B0[4], bB0 + cB1c);
            LDSM4(&B1[0], bB1 + cB0c);
            LDSM4(&B1[4], bB1 + cB1c);
            bB0 += 1024; bB1 += 1024;

            float C[4] = {0.f, 0.f, 0.f, 0.f};
            // small terms first: a0*b1 / a1*b0 interleaved, then a0*b0
            #pragma unroll
            for (int kt = 0; kt < 4; kt++) {
                uint32_t A1f[4];
                const uint32_t col = ((uint32_t)(kt * 32) + cA) ^ xr;
                LDSM4(A1f, baseA1 + col);
                mma16816(C, Af[kt], &B1[2 * kt]);   // a0*b1
                mma16816(C, A1f,    &B0[2 * kt]);   // a1*b0
            }
            #pragma unroll
            for (int kt = 0; kt < 4; kt++)
                mma16816(C, Af[kt], &B0[2 * kt]);   // a0*b0 (dominant, last)

            const int ca = j * 8 + kb;
            const float e2a = e2s[ca], e2b = e2s[ca + 1];
            const float d00 = __fadd_rn(__fsub_rn(z2a, C[0] * TWO_DOT_SCALE), e2a);
            const float d01 = __fadd_rn(__fsub_rn(z2a, C[1] * TWO_DOT_SCALE), e2b);
            const float d10 = __fadd_rn(__fsub_rn(z2b, C[2] * TWO_DOT_SCALE), e2a);
            const float d11 = __fadd_rn(__fsub_rn(z2b, C[3] * TWO_DOT_SCALE), e2b);
            if (d00 < bv0) { bv0 = d00; bi0 = ca; }
            if (d01 < bv0) { bv0 = d01; bi0 = ca + 1; }
            if (d10 < bv1) { bv1 = d10; bi1 = ca; }
            if (d11 < bv1) { bv1 = d11; bi1 = ca + 1; }
        }

        // quad reduce (min, lowest index on tie), write partials to global
        #pragma unroll
        for (int h = 0; h < 2; h++) {
            float v = h ? bv1 : bv0;
            int   i = h ? bi1 : bi0;
            #pragma unroll
            for (int s = 1; s <= 2; s <<= 1) {
                const float ov = __shfl_xor_sync(0xFFFFFFFFu, v, s);
                const int   oi = __shfl_xor_sync(0xFFFFFFFFu, i, s);
                if (ov < v || (ov == v && oi < i)) { v = ov; i = oi; }
            }
            if ((l & 3) == 0) {
                const int row = mrow0 + lr + h * 8;
                g_part[quarter][(size_t)tile * MT + row] =
                    make_float2(v, (float)(quarter * KQ + i));
            }
        }
    }
}

// ---------------- merge quarters, gather codes, write outputs --------------
#define B_ROWS_PER_CTA 16
#define GRID_B (NROWS / B_ROWS_PER_CTA)   // 8192

__global__ __launch_bounds__(TPB, 8)
void vq_merge_gather_kernel(const float* __restrict__ emb,
                            float* __restrict__ out,
                            long long out_size) {
    __shared__ int sidx[B_ROWS_PER_CTA];

    const int tid  = threadIdx.x;
    const int rloc = tid >> 4;
    const int q    = tid & 15;
    const long long row0 = (long long)blockIdx.x * B_ROWS_PER_CTA;

    if (tid < B_ROWS_PER_CTA) {
        const long long n = row0 + tid;
        float2 best = g_part[0][n];
        #pragma unroll
        for (int qq = 1; qq < 4; qq++) {     // ascending quarter, strict <
            const float2 p = g_part[qq][n];  // => first-index tiebreak
            if (p.x < best.x) best = p;
        }
        sidx[tid] = (int)best.y;
    }
    __syncthreads();

    const long long n   = row0 + rloc;
    const int idx       = sidx[rloc];
    const float4 v      = ((const float4*)(emb + (long long)idx * DDIM))[q];
    const long long ND  = (long long)NROWS * DDIM;
    const long long off = n * DDIM + q * 4;

    if (out_size >= ND)      *((float4*)(out + off))      = v;  // z_q_st
    if (out_size >= 2 * ND)  *((float4*)(out + ND + off)) = v;  // z_q

    if (q == 0) {   // indices as float (0..511 exact)
        if (out_size >= 2 * ND + NROWS)      out[2 * ND + n] = (float)idx;
        else if (out_size == ND + NROWS)     out[ND + n]     = (float)idx;
        else if (out_size == NROWS)          out[n]          = (float)idx;
    }
}

// ---------------------------------------------------------------------------
extern "C" void kernel_launch(void* const* d_in, const int* in_sizes, int n_in,
                              void* d_out, int out_size) {
    const float* z   = (const float*)d_in[0];
    const float* emb = (const float*)d_in[1];
    if (n_in >= 2 && in_sizes[0] == KCB * DDIM && in_sizes[1] == NROWS * DDIM) {
        z   = (const float*)d_in[1];
        emb = (const float*)d_in[0];
    }

    static int configured = -1;
    if (configured < 0) {
        cudaFuncSetAttribute(vq_main_kernel,
                             cudaFuncAttributeMaxDynamicSharedMemorySize, SM_TOTAL);
        cudaFuncSetAttribute(vq_zprep_kernel,
                             cudaFuncAttributeMaxDynamicSharedMemorySize, ZP_TOTAL);
        configured = 1;
    }

    vq_zprep_kernel<<<NTILES, TPB, ZP_TOTAL>>>(z);
    vq_main_kernel<<<GRID_MAIN, TPB, SM_TOTAL>>>(emb);
    vq_merge_gather_kernel<<<GRID_B, TPB>>>(emb, (float*)d_out,
                                            (long long)out_size);
}